// round 8
// baseline (speedup 1.0000x reference)
#include <cuda_runtime.h>
#include <cstdint>
#include <cstddef>

// CTC loss (faithful to reference incl. input_len = C bug).
// B=512, T=512 (row stride), C=128, Tu=128, L=64, S=129, blank=127.
// TWO batch rows per warp (interleaved chains hide SHFL/LDS/REDUX latency).
// Lane holds states 4*lane+j (j=0..3) of each row, lane31 also state 128.
// Linear domain, power-of-2 rescale per 8 steps, 128 uniform steps from
// virtual init a0=1@lane0. q's read inline from cp.async-staged smem.

#define B_    512
#define T_    512
#define C_    128
#define L_    64
#define BLANK 127
#define EPSF  (1e-7f)
#define LN2F  0.69314718055994530942f

#define CHUNK  8
#define NBUF   4
#define NCHUNK 16        // 128 timesteps / CHUNK
#define DEPTH  3

__device__ __forceinline__ void cpasync16(uint32_t saddr, const void* g) {
    asm volatile("cp.async.cg.shared.global [%0], [%1], 16;" :: "r"(saddr), "l"(g));
}
__device__ __forceinline__ void cp_commit() { asm volatile("cp.async.commit_group;"); }
__device__ __forceinline__ void cp_wait2()  { asm volatile("cp.async.wait_group 2;"); }

__device__ __forceinline__ int redux_max(int v) {
    int r; asm volatile("redux.sync.max.s32 %0, %1, 0xffffffff;" : "=r"(r) : "r"(v));
    return r;
}

__global__ __launch_bounds__(32)
void ctc_kernel(const int* __restrict__ y_true,
                const float* __restrict__ y_pred,
                float* __restrict__ out)
{
    const unsigned FULL = 0xffffffffu;
    const int lane = threadIdx.x & 31;
    const int bA   = blockIdx.x * 2;
    const int bB   = bA + 1;

    __shared__ float sm[2][NBUF][CHUNK][C_];
    const uint32_t smb = (uint32_t)__cvta_generic_to_shared(&sm[0][0][0][0]);

    const float* __restrict__ rowA = y_pred + (size_t)bA * T_ * C_;
    const float* __restrict__ rowB = y_pred + (size_t)bB * T_ * C_;

    // labels (coalesced int2): lane -> labels 2*lane, 2*lane+1
    const int2 lA = ((const int2*)(y_true + bA * L_))[lane];
    const int2 lB = ((const int2*)(y_true + bB * L_))[lane];
    const int lA0 = lA.x, lA1 = lA.y, lB0 = lB.x, lB1 = lB.y;
    const int lAp = __shfl_up_sync(FULL, lA1, 1);
    const int lBp = __shfl_up_sync(FULL, lB1, 1);
    const float skA1 = (lane > 0 && lA0 != lAp) ? 1.f : 0.f;
    const float skA3 = (lA1 != lA0) ? 1.f : 0.f;
    const float skB1 = (lane > 0 && lB0 != lBp) ? 1.f : 0.f;
    const float skB3 = (lB1 != lB0) ? 1.f : 0.f;

    // ---- staging: one chunk = 8 timesteps x 512B for BOTH rows ---------------
    auto issue_chunk = [&](int c) {
        const int buf = c & (NBUF - 1);
        const float* gA = rowA + (size_t)c * CHUNK * C_ + lane * 4;
        const float* gB = rowB + (size_t)c * CHUNK * C_ + lane * 4;
        const uint32_t sA = smb + (uint32_t)((0 * NBUF + buf) * CHUNK * C_ + lane * 4) * 4;
        const uint32_t sB = smb + (uint32_t)((1 * NBUF + buf) * CHUNK * C_ + lane * 4) * 4;
        #pragma unroll
        for (int j = 0; j < CHUNK; ++j) {
            cpasync16(sA + j * C_ * 4, gA + j * C_);
            cpasync16(sB + j * C_ * 4, gB + j * C_);
        }
    };

    // ---- alpha state, both rows: virtual init => 128 uniform steps ----------
    const float one0 = (lane == 0) ? 1.f : 0.f;
    float a0 = one0, a1 = 0.f, a2 = 0.f, a3 = 0.f, a4 = 0.f, nA = 0.f;
    float c0 = one0, c1 = 0.f, c2 = 0.f, c3 = 0.f, c4 = 0.f, nB = 0.f;
    int etA = 0, etB = 0;

    // ---- pipeline prologue ----------------------------------------------------
    #pragma unroll
    for (int k = 0; k < DEPTH; ++k) { issue_chunk(k); cp_commit(); }

    for (int c = 0; c < NCHUNK; ++c) {
        if (c + DEPTH < NCHUNK) issue_chunk(c + DEPTH);
        cp_commit();
        cp_wait2(); __syncwarp();

        const int buf = c & (NBUF - 1);
        const float* sA = &sm[0][buf][0][0];
        const float* sB = &sm[1][buf][0][0];

        #pragma unroll
        for (int j = 0; j < CHUNK; ++j) {
            // row A q's
            const float qA0 = sA[j * C_ + lA0]   + EPSF;
            const float qA1 = sA[j * C_ + lA1]   + EPSF;
            const float qAB = sA[j * C_ + BLANK] + EPSF;
            // row B q's
            const float qB0 = sB[j * C_ + lB0]   + EPSF;
            const float qB1 = sB[j * C_ + lB1]   + EPSF;
            const float qBB = sB[j * C_ + BLANK] + EPSF;

            // row A update
            const float na0 = (a0 + nA) * qAB;
            const float na1 = fmaf(a1 + a0, qA0, (skA1 * qA0) * nA);
            const float na2 = (a2 + a1) * qAB;
            const float na3 = fmaf(a3 + a2, qA1, (skA3 * qA1) * a1);
            const float na4 = (a4 + a3) * qAB;
            a0 = na0; a1 = na1; a2 = na2; a3 = na3; a4 = na4;
            const float tA = __shfl_up_sync(FULL, a3, 1);

            // row B update (executes in row A's shfl shadow)
            const float nc0 = (c0 + nB) * qBB;
            const float nc1 = fmaf(c1 + c0, qB0, (skB1 * qB0) * nB);
            const float nc2 = (c2 + c1) * qBB;
            const float nc3 = fmaf(c3 + c2, qB1, (skB3 * qB1) * c1);
            const float nc4 = (c4 + c3) * qBB;
            c0 = nc0; c1 = nc1; c2 = nc2; c3 = nc3; c4 = nc4;
            const float tB = __shfl_up_sync(FULL, c3, 1);

            nA = (lane == 0) ? 0.f : tA;
            nB = (lane == 0) ? 0.f : tB;
        }

        // power-of-two rescale, both rows (alpha >= 0 -> s32-monotonic bits)
        {
            float mA = fmaxf(fmaxf(a0, a1), fmaxf(fmaxf(a2, a3), a4));
            float mB = fmaxf(fmaxf(c0, c1), fmaxf(fmaxf(c2, c3), c4));
            const int rA = redux_max(__float_as_int(mA));
            const int rB = redux_max(__float_as_int(mB));
            const int eA = (rA >> 23) - 127;
            const int eB = (rB >> 23) - 127;
            const float sAc = __int_as_float((127 - eA) << 23);   // 2^-eA
            const float sBc = __int_as_float((127 - eB) << 23);
            a0 *= sAc; a1 *= sAc; a2 *= sAc; a3 *= sAc; a4 *= sAc; nA *= sAc;
            c0 *= sBc; c1 *= sBc; c2 *= sBc; c3 *= sBc; c4 *= sBc; nB *= sBc;
            etA += eA; etB += eB;
        }
    }

    // ---- loss = -( ln(alpha[127] + alpha[128]) + etot*ln2 ) ------------------
    if (lane == 31) {
        out[bA] = -(__logf(a3 + a4) + (float)etA * LN2F);
        out[bB] = -(__logf(c3 + c4) + (float)etB * LN2F);
    }
}

extern "C" void kernel_launch(void* const* d_in, const int* in_sizes, int n_in,
                              void* d_out, int out_size)
{
    const int* y_true;
    const float* y_pred;
    if (n_in >= 2 && in_sizes[0] == B_ * L_) {
        y_true = (const int*)d_in[0];
        y_pred = (const float*)d_in[1];
    } else {
        y_true = (const int*)d_in[1];
        y_pred = (const float*)d_in[0];
    }
    float* out = (float*)d_out;

    ctc_kernel<<<B_ / 2, 32>>>(y_true, y_pred, out);
}